// round 8
// baseline (speedup 1.0000x reference)
#include <cuda_runtime.h>
#include <math.h>

#define NKEY 128            // NUM_IMGS(8) * NUM_CLASSES(16)
#define NUM_CLASSES 16
#define NT 256              // threads per block
#define CAP 256             // max group size (mean ~64; Poisson tail ≪ 256)

// cross-call accumulator state (zero at load; self-resetting each call)
__device__ float g_acc;
__device__ int   g_done;

__global__ __launch_bounds__(NT)
void k_fused(const float* __restrict__ preds,
             const float* __restrict__ scores,
             const int*   __restrict__ labels,
             const int*   __restrict__ batch,
             float* __restrict__ out, int n, float inv_n) {
    __shared__ int    mlist[CAP];
    __shared__ float4 sa[CAP];      // {cx, cy, inv(2sig^2), score}
    __shared__ float2 sv[CAP];      // {cos4t, sin4t}
    __shared__ int    s_cnt;
    __shared__ float  red[NT / 32];

    const int mykey = blockIdx.x;   // one block per (batch, class) key
    const int t     = threadIdx.x;
    const int lane  = t & 31;
    const int wib   = t >> 5;

    if (t == 0) s_cnt = 0;
    __syncthreads();

    // ---- P1: scan keys, warp-ballot compaction of matching indices ----
    // (lightweight: 2 coalesced int loads + compare per element; no divergence
    //  in the heavy math path)
    for (int i = t; i < n; i += NT) {
        int key = batch[i] * NUM_CLASSES + labels[i];
        bool m = (key == mykey);
        unsigned mask = __ballot_sync(0xffffffffu, m);
        if (m) {
            int leader = __ffs(mask) - 1;
            int base = 0;
            if (lane == leader) base = atomicAdd(&s_cnt, __popc(mask));
            base = __shfl_sync(mask, base, leader);
            int off = __popc(mask & ((1u << lane) - 1));
            int idx = base + off;
            if (idx < CAP) mlist[idx] = i;
        }
    }
    __syncthreads();
    const int g = min(s_cnt, CAP);

    // ---- P2: divergence-free precompute on the compacted member list ----
    if (t < g) {
        int i = mlist[t];
        const float* p = preds + 5 * i;
        float cx = p[0], cy = p[1], w = p[2], h = p[3], th = p[4];
        float scale = fminf(fmaxf(sqrtf(w * h), 16.0f), 800.0f);
        float sig = 2.0f * scale;                      // K_RADIUS = 2
        float inv = __fdividef(1.0f, 2.0f * sig * sig);
        float sn, cs;
        __sincosf(4.0f * th, &sn, &cs);                // |arg| <= 4*pi
        sa[t] = make_float4(cx, cy, inv, scores[i]);   // SCORE_ALPHA = 1
        sv[t] = make_float2(cs, sn);
    }
    __syncthreads();

    // ---- P3: thread-per-point sweep; uniform j -> broadcast LDS ----
    float chaos = 0.0f;
    if (t < g) {
        float4 a = sa[t];
        float den = 0.0f, nx = 0.0f, ny = 0.0f;
        #pragma unroll 4
        for (int j = 0; j < g; ++j) {
            float4 b = sa[j];
            float2 v = sv[j];
            float dx = a.x - b.x;
            float dy = a.y - b.y;
            float wgt = __expf(-(dx * dx + dy * dy) * a.z) * b.w;
            den += wgt;
            nx  += wgt * v.x;
            ny  += wgt * v.y;
        }
        chaos = 1.0f - sqrtf(nx * nx + ny * ny) / den;
    }

    // ---- P4: block reduce + global accumulate + last-block finalize ----
    float v = chaos;
    #pragma unroll
    for (int o = 16; o; o >>= 1) v += __shfl_xor_sync(0xffffffffu, v, o);
    if (lane == 0) red[wib] = v;
    __syncthreads();
    if (t < NT / 32) {
        v = red[t];
        v += __shfl_xor_sync(0xffu, v, 4);
        v += __shfl_xor_sync(0xffu, v, 2);
        v += __shfl_xor_sync(0xffu, v, 1);
        if (t == 0) {
            atomicAdd(&g_acc, v);
            __threadfence();
            int tk = atomicAdd(&g_done, 1);
            if (tk == NKEY - 1) {                      // last block finalizes
                float tot = atomicAdd(&g_acc, 0.0f);   // read after all adds
                *out = tot * inv_n;                    // LOSS_WEIGHT = 1
                g_acc = 0.0f;                          // reset for next replay
                g_done = 0;
            }
        }
    }
}

extern "C" void kernel_launch(void* const* d_in, const int* in_sizes, int n_in,
                              void* d_out, int out_size) {
    const float* preds  = (const float*)d_in[0];
    const float* scores = (const float*)d_in[1];
    const int*   labels = (const int*)d_in[2];
    const int*   batch  = (const int*)d_in[3];
    float* out = (float*)d_out;
    int n = in_sizes[1];                 // pos_scores element count = N

    k_fused<<<NKEY, NT>>>(preds, scores, labels, batch, out, n, 1.0f / (float)n);
}

// round 9
// speedup vs baseline: 1.3950x; 1.3950x over previous
#include <cuda_runtime.h>
#include <math.h>

#define NKEY 128            // NUM_IMGS(8) * NUM_CLASSES(16)
#define NUM_CLASSES 16
#define NB 128              // blocks (<=148 SMs -> co-resident, spin-safe)
#define NT 256              // threads per block
#define PPB 64              // points per block chunk (8192/128)
#define CAP 256             // slots per key

// ---- device scratch (no allocations; monotonic/self-resetting state) ----
__device__ float4 g_a[NKEY * CAP];   // {cx, cy, inv(2sig^2), score}
__device__ float2 g_v[NKEY * CAP];   // {cos4t, sin4t}
__device__ int    g_cnt[NKEY];       // zero at load; block b resets slot b in P2
__device__ int    g_bar;             // monotonic epoch barrier (never reset)
__device__ float  g_acc;             // zero at load; reset by finalize
__device__ int    g_done;            // zero at load; reset by finalize

__global__ __launch_bounds__(NT)
void k_fused(const float* __restrict__ preds,
             const float* __restrict__ scores,
             const int*   __restrict__ labels,
             const int*   __restrict__ batch,
             float* __restrict__ out, int n, float inv_n) {
    __shared__ float  sraw[PPB * 5];
    __shared__ float4 sa[CAP];
    __shared__ float2 sv[CAP];
    __shared__ float  red[NT / 32];

    const int t    = threadIdx.x;
    const int lane = t & 31;
    const int wib  = t >> 5;
    const int b    = blockIdx.x;

    // ---- P1: precompute + slotted scatter for this block's point chunk(s) ----
    for (int base = b * PPB; base < n; base += NB * PPB) {
        int cnt = min(PPB, n - base);
        // coalesced stage of 5-float records into smem
        for (int j = t; j < cnt * 5; j += NT)
            sraw[j] = preds[base * 5 + j];
        __syncthreads();
        if (t < cnt) {
            int i = base + t;
            float cx = sraw[5 * t],     cy = sraw[5 * t + 1];
            float w  = sraw[5 * t + 2], h  = sraw[5 * t + 3];
            float th = sraw[5 * t + 4];
            float scale = fminf(fmaxf(sqrtf(w * h), 16.0f), 800.0f);
            float sig = 2.0f * scale;                      // K_RADIUS = 2
            float inv = __fdividef(1.0f, 2.0f * sig * sig);
            float sn, cs;
            __sincosf(4.0f * th, &sn, &cs);                // |arg| <= 4*pi
            int key = batch[i] * NUM_CLASSES + labels[i];
            int slot = atomicAdd(&g_cnt[key], 1);
            if (slot < CAP) {
                g_a[key * CAP + slot] = make_float4(cx, cy, inv, scores[i]);
                g_v[key * CAP + slot] = make_float2(cs, sn);  // SCORE_ALPHA = 1
            }
        }
        __syncthreads();
    }

    // ---- monotonic epoch grid barrier (no reset -> replay-safe) ----
    __shared__ int s_target;
    __threadfence();                       // publish P1 writes
    if (t == 0) {
        int ticket = atomicAdd(&g_bar, 1);
        int target = (ticket / NB + 1) * NB;
        s_target = target;
        while (*(volatile int*)&g_bar < target) { }
    }
    __syncthreads();
    __threadfence();                       // acquire P1 writes

    // ---- P2: block b sweeps key b ----
    const int mykey = b;
    int g = min(g_cnt[mykey], CAP);
    const int gbase = mykey * CAP;
    for (int j = t; j < g; j += NT) {
        sa[j] = g_a[gbase + j];
        sv[j] = g_v[gbase + j];
    }
    __syncthreads();
    if (t == 0) g_cnt[mykey] = 0;          // reset for next replay

    float chaos = 0.0f;
    if (t < g) {
        float4 a = sa[t];
        float den = 0.0f, nx = 0.0f, ny = 0.0f;
        #pragma unroll 4
        for (int j = 0; j < g; ++j) {      // uniform j -> broadcast LDS
            float4 bb = sa[j];
            float2 v  = sv[j];
            float dx = a.x - bb.x;
            float dy = a.y - bb.y;
            float wgt = __expf(-(dx * dx + dy * dy) * a.z) * bb.w;
            den += wgt;
            nx  += wgt * v.x;
            ny  += wgt * v.y;
        }
        chaos = 1.0f - sqrtf(nx * nx + ny * ny) / den;
    }

    // ---- block reduce + global accumulate + last-block finalize ----
    float v = chaos;
    #pragma unroll
    for (int o = 16; o; o >>= 1) v += __shfl_xor_sync(0xffffffffu, v, o);
    if (lane == 0) red[wib] = v;
    __syncthreads();
    if (t < NT / 32) {
        v = red[t];
        v += __shfl_xor_sync(0xffu, v, 4);
        v += __shfl_xor_sync(0xffu, v, 2);
        v += __shfl_xor_sync(0xffu, v, 1);
        if (t == 0) {
            atomicAdd(&g_acc, v);
            __threadfence();
            int tk = atomicAdd(&g_done, 1);
            if (tk == NB - 1) {                        // last block finalizes
                float tot = atomicAdd(&g_acc, 0.0f);   // read after all adds
                *out = tot * inv_n;                    // LOSS_WEIGHT = 1
                g_acc = 0.0f;
                g_done = 0;
            }
        }
    }
}

extern "C" void kernel_launch(void* const* d_in, const int* in_sizes, int n_in,
                              void* d_out, int out_size) {
    const float* preds  = (const float*)d_in[0];
    const float* scores = (const float*)d_in[1];
    const int*   labels = (const int*)d_in[2];
    const int*   batch  = (const int*)d_in[3];
    float* out = (float*)d_out;
    int n = in_sizes[1];                 // pos_scores element count = N

    k_fused<<<NB, NT>>>(preds, scores, labels, batch, out, n, 1.0f / (float)n);
}